// round 11
// baseline (speedup 1.0000x reference)
#include <cuda_runtime.h>
#include <cuda_bf16.h>
#include <cstdint>
#include <cstddef>

// Problem constants
#define BB     32
#define TT     2048
#define FIN    63
#define FDIM   64
#define LUDIM  640
#define NCH    64      // chunks of 32 timesteps
#define TCH    32
#define NCHAIN 2048

// smem byte offsets (fused kernel) — total 110,592 B -> 2 CTAs/SM
#define XSTR   72      // dX row stride (bf16 elems), pad for conflict-free ldsm
#define KSTR   72      // K stage stride (bf16 elems): 64 cols + 8 pad
#define PSTR   648     // sP row stride (floats)
#define OFF_XH 0
#define OFF_XL 4608            // 32*72*2
#define OFF_KH 9216
#define OFF_KL 18432           // + 64*72*2 = 9216
#define OFF_SP 27648
#define SMEM_TOTAL (OFF_SP + TCH * PSTR * 4)   // 27648 + 82944 = 110592
// 4 sub-chunk SigMaps per chain staged over the K region (4*64*17*4 = 17408 B)
#define OFF_MAPS OFF_KH

// Precomputed bf16 hi/lo split of kernel, [f][lu]
__device__ __nv_bfloat16 g_KH[FDIM * LUDIM];
__device__ __nv_bfloat16 g_KL[FDIM * LUDIM];
// g_W layout: [chain][c][17]  (combine reads coalesced)
__device__ float g_W[(size_t)NCHAIN * NCH * 17];

// ---------------- PTX helpers ----------------
__device__ __forceinline__ uint32_t smem_u32(const void* p) {
    uint32_t a;
    asm("{ .reg .u64 t; cvta.to.shared.u64 t, %1; cvt.u32.u64 %0, t; }" : "=r"(a) : "l"(p));
    return a;
}
__device__ __forceinline__ void ldsm_x4(uint32_t& r0, uint32_t& r1, uint32_t& r2, uint32_t& r3,
                                        uint32_t addr) {
    asm volatile("ldmatrix.sync.aligned.m8n8.x4.shared.b16 {%0,%1,%2,%3}, [%4];"
                 : "=r"(r0), "=r"(r1), "=r"(r2), "=r"(r3) : "r"(addr));
}
__device__ __forceinline__ void ldsm_x4t(uint32_t& r0, uint32_t& r1, uint32_t& r2, uint32_t& r3,
                                         uint32_t addr) {
    asm volatile("ldmatrix.sync.aligned.m8n8.x4.trans.shared.b16 {%0,%1,%2,%3}, [%4];"
                 : "=r"(r0), "=r"(r1), "=r"(r2), "=r"(r3) : "r"(addr));
}
__device__ __forceinline__ void mma_bf16(float* c, const uint32_t* a, uint32_t b0, uint32_t b1) {
    asm volatile(
        "mma.sync.aligned.m16n8k16.row.col.f32.bf16.bf16.f32 "
        "{%0,%1,%2,%3}, {%4,%5,%6,%7}, {%8,%9}, {%0,%1,%2,%3};"
        : "+f"(c[0]), "+f"(c[1]), "+f"(c[2]), "+f"(c[3])
        : "r"(a[0]), "r"(a[1]), "r"(a[2]), "r"(a[3]), "r"(b0), "r"(b1));
}

// ---------------- Chen map: 17 coefficients ----------------
struct SigMap {
    float Y0,S2,S5,S9,W54,W98,W987,E1,E3,E4,E43,E6,E7,E76,E8,E87,E876;
};

// C = B after A (A covers earlier time)
__device__ __forceinline__ SigMap sig_compose(const SigMap& A, const SigMap& B) {
    SigMap C;
    C.E1   = A.E1 + B.E1;
    C.E3   = A.E3 + B.E3;
    C.E6   = A.E6 + B.E6;
    C.E4   = A.E4 + B.E4;
    C.E43  = A.E43 + A.E3 * B.E4 + B.E43;
    C.E7   = A.E7 + B.E7;
    C.E76  = A.E76 + A.E6 * B.E7 + B.E76;
    C.E8   = A.E8 + B.E8;
    C.E87  = A.E87 + A.E7 * B.E8 + B.E87;
    C.E876 = A.E876 + A.E76 * B.E8 + A.E6 * B.E87 + B.E876;
    C.S2   = A.S2 + B.S2;
    C.S5   = A.S5 + B.S5;
    C.S9   = A.S9 + B.S9;
    C.W54  = A.W54 + A.E4 * B.S5 + B.W54;
    C.W98  = A.W98 + A.E8 * B.S9 + B.W98;
    C.W987 = A.W987 + A.E87 * B.S9 + A.E7 * B.W98 + B.W987;
    C.Y0   = A.Y0 + B.Y0 + A.E1 * B.S2 + A.E43 * B.S5 + A.E3 * B.W54
           + A.E876 * B.S9 + A.E76 * B.W98 + A.E6 * B.W987;
    return C;
}

__device__ __forceinline__ SigMap sig_load_f(const float* mp) {
    SigMap m;
    m.Y0  = mp[0];  m.S2  = mp[1];  m.S5  = mp[2];  m.S9  = mp[3];
    m.W54 = mp[4];  m.W98 = mp[5];  m.W987= mp[6];
    m.E1  = mp[7];  m.E3  = mp[8];  m.E4  = mp[9];  m.E43 = mp[10];
    m.E6  = mp[11]; m.E7  = mp[12]; m.E76 = mp[13];
    m.E8  = mp[14]; m.E87 = mp[15]; m.E876= mp[16];
    return m;
}

// ---------------- Prep: K -> bf16 hi/lo in gmem ----------------
extern "C" __global__ void __launch_bounds__(256)
lrsig_prep(const float* __restrict__ kern)
{
    int i = blockIdx.x * 256 + threadIdx.x;
    if (i < FDIM * LUDIM) {
        float v = kern[i];
        __nv_bfloat16 hi = __float2bfloat16(v);
        g_KH[i] = hi;
        g_KL[i] = __float2bfloat16(v - __bfloat162float(hi));
    }
}

// ---------------- Fused kernel: dX GEMM (m = dX @ K) + chunk scan ----------------
// Grid (NCH, BB) = (64, 32), 256 threads, 2 CTAs/SM (110.6 KB smem).
// 8 warps: wm = w&1 (16-row m half), wn = w>>1 (n16 quarter of 64-col stage).
// sP holds the DIFFS m[t][lu] directly (m = (X[t]-X[t-1])·K; m[0] = 0).
extern "C" __global__ void __launch_bounds__(256, 2)
lrsig_fused(const float* __restrict__ x, const float* __restrict__ kern)
{
    extern __shared__ char smem[];
    float* sP = reinterpret_cast<float*>(smem + OFF_SP);
    const uint32_t sb = smem_u32(smem);

    const int tid  = threadIdx.x;
    const int lane = tid & 31;
    const int w    = tid >> 5;
    const int wm   = w & 1;
    const int wn   = w >> 1;
    const int c    = blockIdx.x;
    const int b    = blockIdx.y;
    const int t0   = c * TCH;

    // ---- dX tile (hi/lo bf16 split), [t][f], stride 72; exact fp32 diff ----
    for (int e = tid; e < TCH * FDIM; e += 256) {
        int tl = e >> 6, f = e & 63;
        int t = t0 + tl;
        float v;
        if (t == 0)      v = 0.0f;                                   // m[0] = 0
        else if (f < FIN) {
            const float* xr = x + ((size_t)b * TT + t) * FIN + f;
            v = xr[0] - xr[-FIN];
        } else            v = 2.0f / 2047.0f;                        // d(time)
        __nv_bfloat16 hi = __float2bfloat16(v);
        __nv_bfloat16 lo = __float2bfloat16(v - __bfloat162float(hi));
        int off = (tl * XSTR + f) * 2;
        *reinterpret_cast<__nv_bfloat16*>(smem + OFF_XH + off) = hi;
        *reinterpret_cast<__nv_bfloat16*>(smem + OFF_XL + off) = lo;
    }
    __syncthreads();

    // ---- Preload A fragments once (32 regs; reused across all 10 stages) ----
    const uint32_t a_off = (uint32_t)((lane & 15) * XSTR + ((lane >> 4) << 3)) * 2;
    uint32_t Ah[4][4], Al[4][4];
#pragma unroll
    for (int ks = 0; ks < 4; ks++) {
        uint32_t ra = (uint32_t)(wm * 16 * XSTR + ks * 16) * 2 + a_off;
        ldsm_x4(Ah[ks][0], Ah[ks][1], Ah[ks][2], Ah[ks][3], sb + OFF_XH + ra);
        ldsm_x4(Al[ks][0], Al[ks][1], Al[ks][2], Al[ks][3], sb + OFF_XL + ra);
    }

    const uint32_t b_off = (uint32_t)((((lane >> 3) & 1) * 8 + (lane & 7)) * KSTR
                                      + ((lane >> 4) << 3)) * 2;

    // ---- Stage loop: 10 stages of 64 lu cols (one signature level each) ----
    for (int s = 0; s < 10; s++) {
        __syncthreads();   // prior stage's ldsm reads complete before refill
        // K stage fill: uint4 copies of precomputed bf16 (2/thread/buffer)
        {
            const uint4* srcH = reinterpret_cast<const uint4*>(g_KH);
            const uint4* srcL = reinterpret_cast<const uint4*>(g_KL);
            uint4* dstH = reinterpret_cast<uint4*>(smem + OFF_KH);
            uint4* dstL = reinterpret_cast<uint4*>(smem + OFF_KL);
            for (int e = tid; e < FDIM * 8; e += 256) {   // 64 f-rows x 8 uint4
                int f = e >> 3, v = e & 7;
                dstH[f * 9 + v] = srcH[f * 80 + s * 8 + v];
                dstL[f * 9 + v] = srcL[f * 80 + s * 8 + v];
            }
        }
        __syncthreads();

        float C[2][4];
#pragma unroll
        for (int p = 0; p < 2; p++)
#pragma unroll
            for (int i = 0; i < 4; i++) C[p][i] = 0.0f;

#pragma unroll
        for (int ks = 0; ks < 4; ks++) {
            uint32_t rb = (uint32_t)(ks * 16 * KSTR + wn * 16) * 2 + b_off;
            uint32_t Bh[4], Bl[4];
            ldsm_x4t(Bh[0], Bh[1], Bh[2], Bh[3], sb + OFF_KH + rb);
            ldsm_x4t(Bl[0], Bl[1], Bl[2], Bl[3], sb + OFF_KL + rb);
#pragma unroll
            for (int p = 0; p < 2; p++) {
                mma_bf16(C[p], Ah[ks], Bh[p * 2], Bh[p * 2 + 1]);
                mma_bf16(C[p], Al[ks], Bh[p * 2], Bh[p * 2 + 1]);
                mma_bf16(C[p], Ah[ks], Bl[p * 2], Bl[p * 2 + 1]);
            }
        }

        // Epilogue into sP rows 0..31 (row = t-local)
        {
            int r = wm * 16 + (lane >> 2);
#pragma unroll
            for (int p = 0; p < 2; p++) {
                int col = s * 64 + wn * 16 + p * 8 + (lane & 3) * 2;
                float* q0 = sP + (size_t)r * PSTR + col;
                float* q1 = sP + (size_t)(r + 8) * PSTR + col;
                *reinterpret_cast<float2*>(q0) = make_float2(C[p][0], C[p][1]);
                *reinterpret_cast<float2*>(q1) = make_float2(C[p][2], C[p][3]);
            }
        }
    }
    __syncthreads();

    // ---- 4-way scan: thread (u, q) scans rows q*8 .. q*8+7 (m directly) ----
    float* sMaps = reinterpret_cast<float*>(smem + OFF_MAPS);
    {
        const int u = tid & 63;
        const int q = tid >> 6;        // 0..3
        const int r0 = q * 8;

        float e1=0.f,e3=0.f,e4=0.f,e43=0.f,e6=0.f,e7=0.f,e76=0.f,e8=0.f,e87=0.f,e876=0.f;
        float S2=0.f,S5=0.f,S9=0.f,W21=0.f,W54=0.f,W543=0.f,W98=0.f,W987=0.f,W9876=0.f,y0=0.f;

#pragma unroll
        for (int i = 0; i < 8; i++) {
            const float* p = sP + (size_t)(r0 + i) * PSTR + u;
            float m[10];
#pragma unroll
            for (int l = 0; l < 10; l++) m[l] = p[l * 64];
            // All RHS use pre-update (exclusive) values.
            y0   += m[0];
            W21   = fmaf(m[2], e1,   W21);   S2 += m[2];
            W54   = fmaf(m[5], e4,   W54);
            W543  = fmaf(m[5], e43,  W543);  S5 += m[5];
            W98   = fmaf(m[9], e8,   W98);
            W987  = fmaf(m[9], e87,  W987);
            W9876 = fmaf(m[9], e876, W9876); S9 += m[9];
            e43   = fmaf(m[4], e3,   e43);
            e876  = fmaf(m[8], e76,  e876);
            e87   = fmaf(m[8], e7,   e87);
            e76   = fmaf(m[7], e6,   e76);
            e1 += m[1]; e3 += m[3]; e4 += m[4];
            e6 += m[6]; e7 += m[7]; e8 += m[8];
        }

        float* mp = sMaps + (size_t)(q * 64 + u) * 17;
        mp[0]  = y0 + W21 + W543 + W9876;
        mp[1]  = S2;  mp[2]  = S5;  mp[3]  = S9;
        mp[4]  = W54; mp[5]  = W98; mp[6]  = W987;
        mp[7]  = e1;  mp[8]  = e3;  mp[9]  = e4;
        mp[10] = e43; mp[11] = e6;  mp[12] = e7;
        mp[13] = e76; mp[14] = e8;  mp[15] = e87;
        mp[16] = e876;
    }
    __syncthreads();

    // ---- Compose 4 sub-maps per chain, write g_W[chain][c][17] ----
    if (tid < 64) {
        const int u = tid;
        SigMap R = sig_load_f(sMaps + (size_t)u * 17);
#pragma unroll
        for (int q = 1; q < 4; q++)
            R = sig_compose(R, sig_load_f(sMaps + (size_t)(q * 64 + u) * 17));

        const int chain = b * 64 + u;
        float* wp = g_W + ((size_t)chain * NCH + c) * 17;
        wp[0]  = R.Y0;  wp[1]  = R.S2;  wp[2]  = R.S5;  wp[3]  = R.S9;
        wp[4]  = R.W54; wp[5]  = R.W98; wp[6]  = R.W987;
        wp[7]  = R.E1;  wp[8]  = R.E3;  wp[9]  = R.E4;  wp[10] = R.E43;
        wp[11] = R.E6;  wp[12] = R.E7;  wp[13] = R.E76;
        wp[14] = R.E8;  wp[15] = R.E87; wp[16] = R.E876;
    }
}

// ---------------- Combine: warp-tree composition over 64 chunks ----------------
__device__ __forceinline__ SigMap sig_shfl_down(const SigMap& m, int o) {
    SigMap r;
    r.Y0  = __shfl_down_sync(0xffffffffu, m.Y0,  o);
    r.S2  = __shfl_down_sync(0xffffffffu, m.S2,  o);
    r.S5  = __shfl_down_sync(0xffffffffu, m.S5,  o);
    r.S9  = __shfl_down_sync(0xffffffffu, m.S9,  o);
    r.W54 = __shfl_down_sync(0xffffffffu, m.W54, o);
    r.W98 = __shfl_down_sync(0xffffffffu, m.W98, o);
    r.W987= __shfl_down_sync(0xffffffffu, m.W987,o);
    r.E1  = __shfl_down_sync(0xffffffffu, m.E1,  o);
    r.E3  = __shfl_down_sync(0xffffffffu, m.E3,  o);
    r.E4  = __shfl_down_sync(0xffffffffu, m.E4,  o);
    r.E43 = __shfl_down_sync(0xffffffffu, m.E43, o);
    r.E6  = __shfl_down_sync(0xffffffffu, m.E6,  o);
    r.E7  = __shfl_down_sync(0xffffffffu, m.E7,  o);
    r.E76 = __shfl_down_sync(0xffffffffu, m.E76, o);
    r.E8  = __shfl_down_sync(0xffffffffu, m.E8,  o);
    r.E87 = __shfl_down_sync(0xffffffffu, m.E87, o);
    r.E876= __shfl_down_sync(0xffffffffu, m.E876,o);
    return r;
}

extern "C" __global__ void __launch_bounds__(256)
lrsig_combine(float* __restrict__ out)
{
    const int chain = blockIdx.x * 8 + (threadIdx.x >> 5);
    const int lane  = threadIdx.x & 31;

    // lane folds chunks (2*lane, 2*lane+1), then 5-level tree -> lane 0 exact
    const float* wp = g_W + ((size_t)chain * NCH + 2 * lane) * 17;
    SigMap M = sig_compose(sig_load_f(wp), sig_load_f(wp + 17));

#pragma unroll
    for (int o = 1; o < 32; o <<= 1)
        M = sig_compose(M, sig_shfl_down(M, o));

    if (lane == 0) out[chain] = M.Y0;   // initial state zero -> Y = Y0
}

// ---------------- Launch ----------------
extern "C" void kernel_launch(void* const* d_in, const int* in_sizes, int n_in,
                              void* d_out, int out_size)
{
    const float* x    = (const float*)d_in[0];  // (32, 2048, 63) f32
    const float* kern = (const float*)d_in[1];  // (64, 10, 64)  f32

    cudaFuncSetAttribute(lrsig_fused, cudaFuncAttributeMaxDynamicSharedMemorySize,
                         SMEM_TOTAL);

    lrsig_prep<<<(FDIM * LUDIM + 255) / 256, 256>>>(kern);
    lrsig_fused<<<dim3(NCH, BB), 256, SMEM_TOTAL>>>(x, kern);
    lrsig_combine<<<NCHAIN / 8, 256>>>((float*)d_out);
}

// round 12
// speedup vs baseline: 1.3295x; 1.3295x over previous
#include <cuda_runtime.h>
#include <cuda_bf16.h>
#include <cstdint>
#include <cstddef>

// Problem constants
#define BB     32
#define TT     2048
#define FIN    63
#define FDIM   64
#define LUDIM  640
#define NCH    32      // chunks of 64 timesteps
#define TCH    64
#define NCHAIN 2048

// smem byte offsets (fused kernel) — total 219,136 B, 1 CTA/SM
#define XSTR   72      // dX row stride (bf16 elems)
#define KSTR   136     // K stage stride (bf16 elems) = 17 uint4
#define PSTR   648     // sP row stride (floats); 648 mod 32 = 8 -> rows spread banks
#define OFF_XH 0
#define OFF_XL 9216            // 64*72*2
#define OFF_KH 18432
#define OFF_KL 35840           // +64*136*2 = 17408
#define OFF_SP 53248
#define SMEM_TOTAL (OFF_SP + TCH * PSTR * 4)   // 53248 + 165888 = 219136
// 8 sub-chunk SigMaps per chain staged over the K region (8*64*17*4 = 34816 B)
#define OFF_MAPS OFF_KH

// Precomputed bf16 hi/lo split of kernel, [f][lu]
__device__ __nv_bfloat16 g_KH[FDIM * LUDIM];
__device__ __nv_bfloat16 g_KL[FDIM * LUDIM];
// g_W layout: [chain][c][17]  (combine reads coalesced)
__device__ float g_W[(size_t)NCHAIN * NCH * 17];

// ---------------- PTX helpers ----------------
__device__ __forceinline__ uint32_t smem_u32(const void* p) {
    uint32_t a;
    asm("{ .reg .u64 t; cvta.to.shared.u64 t, %1; cvt.u32.u64 %0, t; }" : "=r"(a) : "l"(p));
    return a;
}
__device__ __forceinline__ void ldsm_x4(uint32_t& r0, uint32_t& r1, uint32_t& r2, uint32_t& r3,
                                        uint32_t addr) {
    asm volatile("ldmatrix.sync.aligned.m8n8.x4.shared.b16 {%0,%1,%2,%3}, [%4];"
                 : "=r"(r0), "=r"(r1), "=r"(r2), "=r"(r3) : "r"(addr));
}
__device__ __forceinline__ void ldsm_x4t(uint32_t& r0, uint32_t& r1, uint32_t& r2, uint32_t& r3,
                                         uint32_t addr) {
    asm volatile("ldmatrix.sync.aligned.m8n8.x4.trans.shared.b16 {%0,%1,%2,%3}, [%4];"
                 : "=r"(r0), "=r"(r1), "=r"(r2), "=r"(r3) : "r"(addr));
}
__device__ __forceinline__ void mma_bf16(float* c, const uint32_t* a, uint32_t b0, uint32_t b1) {
    asm volatile(
        "mma.sync.aligned.m16n8k16.row.col.f32.bf16.bf16.f32 "
        "{%0,%1,%2,%3}, {%4,%5,%6,%7}, {%8,%9}, {%0,%1,%2,%3};"
        : "+f"(c[0]), "+f"(c[1]), "+f"(c[2]), "+f"(c[3])
        : "r"(a[0]), "r"(a[1]), "r"(a[2]), "r"(a[3]), "r"(b0), "r"(b1));
}

// ---------------- Chen map: 17 coefficients ----------------
struct SigMap {
    float Y0,S2,S5,S9,W54,W98,W987,E1,E3,E4,E43,E6,E7,E76,E8,E87,E876;
};

// C = B after A (A covers earlier time)
__device__ __forceinline__ SigMap sig_compose(const SigMap& A, const SigMap& B) {
    SigMap C;
    C.E1   = A.E1 + B.E1;
    C.E3   = A.E3 + B.E3;
    C.E6   = A.E6 + B.E6;
    C.E4   = A.E4 + B.E4;
    C.E43  = A.E43 + A.E3 * B.E4 + B.E43;
    C.E7   = A.E7 + B.E7;
    C.E76  = A.E76 + A.E6 * B.E7 + B.E76;
    C.E8   = A.E8 + B.E8;
    C.E87  = A.E87 + A.E7 * B.E8 + B.E87;
    C.E876 = A.E876 + A.E76 * B.E8 + A.E6 * B.E87 + B.E876;
    C.S2   = A.S2 + B.S2;
    C.S5   = A.S5 + B.S5;
    C.S9   = A.S9 + B.S9;
    C.W54  = A.W54 + A.E4 * B.S5 + B.W54;
    C.W98  = A.W98 + A.E8 * B.S9 + B.W98;
    C.W987 = A.W987 + A.E87 * B.S9 + A.E7 * B.W98 + B.W987;
    C.Y0   = A.Y0 + B.Y0 + A.E1 * B.S2 + A.E43 * B.S5 + A.E3 * B.W54
           + A.E876 * B.S9 + A.E76 * B.W98 + A.E6 * B.W987;
    return C;
}

__device__ __forceinline__ SigMap sig_load_f(const float* mp) {
    SigMap m;
    m.Y0  = mp[0];  m.S2  = mp[1];  m.S5  = mp[2];  m.S9  = mp[3];
    m.W54 = mp[4];  m.W98 = mp[5];  m.W987= mp[6];
    m.E1  = mp[7];  m.E3  = mp[8];  m.E4  = mp[9];  m.E43 = mp[10];
    m.E6  = mp[11]; m.E7  = mp[12]; m.E76 = mp[13];
    m.E8  = mp[14]; m.E87 = mp[15]; m.E876= mp[16];
    return m;
}

// ---------------- Prep: K -> bf16 hi/lo in gmem ----------------
extern "C" __global__ void __launch_bounds__(256)
lrsig_prep(const float* __restrict__ kern)
{
    int i = blockIdx.x * 256 + threadIdx.x;
    if (i < FDIM * LUDIM) {
        float v = kern[i];
        __nv_bfloat16 hi = __float2bfloat16(v);
        g_KH[i] = hi;
        g_KL[i] = __float2bfloat16(v - __bfloat162float(hi));
    }
}

// ---------------- Fused kernel: m = dX @ K (in smem) + 8-way chunk scan ----------------
// Grid (NCH, BB) = (32, 32), 512 threads, 1 CTA/SM.
// 16 warps: wt = w&3 (16-row t quarter), wn = w>>2 (32-col lu quarter of stage).
// sP holds the DIFFS m[t][lu] directly (m = (X[t]-X[t-1])·K; m[0] = 0).
// K stage tiles are register-prefetched one stage ahead (gmem latency overlaps MMA).
extern "C" __global__ void __launch_bounds__(512, 1)
lrsig_fused(const float* __restrict__ x, const float* __restrict__ kern)
{
    extern __shared__ char smem[];
    float* sP = reinterpret_cast<float*>(smem + OFF_SP);
    const uint32_t sb = smem_u32(smem);

    const int tid  = threadIdx.x;
    const int lane = tid & 31;
    const int w    = tid >> 5;
    const int wt   = w & 3;
    const int wn   = w >> 2;
    const int c    = blockIdx.x;
    const int b    = blockIdx.y;
    const int t0   = c * TCH;

    // K prefetch register state: 2 uint4 per buffer per thread covers
    // FDIM*16 = 1024 uint4 per buffer with 512 threads.
    const uint4* srcH = reinterpret_cast<const uint4*>(g_KH);
    const uint4* srcL = reinterpret_cast<const uint4*>(g_KL);
    uint4* dstH = reinterpret_cast<uint4*>(smem + OFF_KH);
    uint4* dstL = reinterpret_cast<uint4*>(smem + OFF_KL);
    const int e0 = tid, e1 = tid + 512;
    const int f0 = e0 >> 4, v0 = e0 & 15;
    const int f1 = e1 >> 4, v1 = e1 & 15;

    // ---- Prefetch stage 0 K into registers (overlaps the dX fill) ----
    uint4 rH0 = srcH[f0 * 80 + v0], rH1 = srcH[f1 * 80 + v1];
    uint4 rL0 = srcL[f0 * 80 + v0], rL1 = srcL[f1 * 80 + v1];

    // ---- dX tile (hi/lo bf16 split), [t][f], stride 72; exact fp32 diff ----
    for (int e = tid; e < TCH * FDIM; e += 512) {
        int tl = e >> 6, f = e & 63;
        int t = t0 + tl;
        float v;
        if (t == 0)      v = 0.0f;                                   // m[0] = 0
        else if (f < FIN) {
            const float* xr = x + ((size_t)b * TT + t) * FIN + f;
            v = xr[0] - xr[-FIN];
        } else            v = 2.0f / 2047.0f;                        // d(time)
        __nv_bfloat16 hi = __float2bfloat16(v);
        __nv_bfloat16 lo = __float2bfloat16(v - __bfloat162float(hi));
        int off = (tl * XSTR + f) * 2;
        *reinterpret_cast<__nv_bfloat16*>(smem + OFF_XH + off) = hi;
        *reinterpret_cast<__nv_bfloat16*>(smem + OFF_XL + off) = lo;
    }
    __syncthreads();

    // ---- Preload A fragments once (32 regs; reused across all 5 stages) ----
    const uint32_t a_off = (uint32_t)((lane & 15) * XSTR + ((lane >> 4) << 3)) * 2;
    uint32_t Ah[4][4], Al[4][4];
#pragma unroll
    for (int ks = 0; ks < 4; ks++) {
        uint32_t ra = (uint32_t)(wt * 16 * XSTR + ks * 16) * 2 + a_off;
        ldsm_x4(Ah[ks][0], Ah[ks][1], Ah[ks][2], Ah[ks][3], sb + OFF_XH + ra);
        ldsm_x4(Al[ks][0], Al[ks][1], Al[ks][2], Al[ks][3], sb + OFF_XL + ra);
    }

    const uint32_t b_off = (uint32_t)((((lane >> 3) & 1) * 8 + (lane & 7)) * KSTR
                                      + ((lane >> 4) << 3)) * 2;

    // ---- Stage loop: 5 stages of 128 lu; K register-prefetch pipeline ----
    for (int s = 0; s < 5; s++) {
        // (first iteration: A-ldsm above already synced; later: epilogue of
        // s-1 and its ldsm reads must finish before K overwrite)
        if (s > 0) __syncthreads();
        // Commit prefetched K stage to smem
        dstH[f0 * 17 + v0] = rH0;  dstH[f1 * 17 + v1] = rH1;
        dstL[f0 * 17 + v0] = rL0;  dstL[f1 * 17 + v1] = rL1;
        __syncthreads();

        // Kick off prefetch of stage s+1 (independent of this stage's MMA)
        if (s < 4) {
            rH0 = srcH[f0 * 80 + (s + 1) * 16 + v0];
            rH1 = srcH[f1 * 80 + (s + 1) * 16 + v1];
            rL0 = srcL[f0 * 80 + (s + 1) * 16 + v0];
            rL1 = srcL[f1 * 80 + (s + 1) * 16 + v1];
        }

        float C[4][4];
#pragma unroll
        for (int nt = 0; nt < 4; nt++)
#pragma unroll
            for (int i = 0; i < 4; i++) C[nt][i] = 0.0f;

#pragma unroll
        for (int ks = 0; ks < 4; ks++)
#pragma unroll
            for (int q = 0; q < 2; q++) {
                uint32_t rb = (uint32_t)(ks * 16 * KSTR + (wn * 32 + q * 16)) * 2 + b_off;
                uint32_t Bh[4], Bl[4];
                ldsm_x4t(Bh[0], Bh[1], Bh[2], Bh[3], sb + OFF_KH + rb);
                ldsm_x4t(Bl[0], Bl[1], Bl[2], Bl[3], sb + OFF_KL + rb);
#pragma unroll
                for (int p = 0; p < 2; p++) {
                    float* cc = C[q * 2 + p];
                    mma_bf16(cc, Ah[ks], Bh[p * 2], Bh[p * 2 + 1]);
                    mma_bf16(cc, Al[ks], Bh[p * 2], Bh[p * 2 + 1]);
                    mma_bf16(cc, Ah[ks], Bl[p * 2], Bl[p * 2 + 1]);
                }
            }

        // Epilogue into sP rows 0..63 (row = t-local)
        {
            int r = wt * 16 + (lane >> 2);
#pragma unroll
            for (int nt = 0; nt < 4; nt++) {
                int col = s * 128 + wn * 32 + nt * 8 + (lane & 3) * 2;
                float* q0 = sP + (size_t)r * PSTR + col;
                float* q1 = sP + (size_t)(r + 8) * PSTR + col;
                *reinterpret_cast<float2*>(q0) = make_float2(C[nt][0], C[nt][1]);
                *reinterpret_cast<float2*>(q1) = make_float2(C[nt][2], C[nt][3]);
            }
        }
    }
    __syncthreads();

    // ---- 8-way scan: thread (u, q) scans rows q*8 .. q*8+7 (m directly) ----
    float* sMaps = reinterpret_cast<float*>(smem + OFF_MAPS);
    {
        const int u = tid & 63;
        const int q = tid >> 6;        // 0..7
        const int r0 = q * 8;

        float e1=0.f,e3=0.f,e4=0.f,e43=0.f,e6=0.f,e7=0.f,e76=0.f,e8=0.f,e87=0.f,e876=0.f;
        float S2=0.f,S5=0.f,S9=0.f,W21=0.f,W54=0.f,W543=0.f,W98=0.f,W987=0.f,W9876=0.f,y0=0.f;

#pragma unroll
        for (int i = 0; i < 8; i++) {
            const float* p = sP + (size_t)(r0 + i) * PSTR + u;
            float m[10];
#pragma unroll
            for (int l = 0; l < 10; l++) m[l] = p[l * 64];
            // All RHS use pre-update (exclusive) values.
            y0   += m[0];
            W21   = fmaf(m[2], e1,   W21);   S2 += m[2];
            W54   = fmaf(m[5], e4,   W54);
            W543  = fmaf(m[5], e43,  W543);  S5 += m[5];
            W98   = fmaf(m[9], e8,   W98);
            W987  = fmaf(m[9], e87,  W987);
            W9876 = fmaf(m[9], e876, W9876); S9 += m[9];
            e43   = fmaf(m[4], e3,   e43);
            e876  = fmaf(m[8], e76,  e876);
            e87   = fmaf(m[8], e7,   e87);
            e76   = fmaf(m[7], e6,   e76);
            e1 += m[1]; e3 += m[3]; e4 += m[4];
            e6 += m[6]; e7 += m[7]; e8 += m[8];
        }

        float* mp = sMaps + (size_t)(q * 64 + u) * 17;
        mp[0]  = y0 + W21 + W543 + W9876;
        mp[1]  = S2;  mp[2]  = S5;  mp[3]  = S9;
        mp[4]  = W54; mp[5]  = W98; mp[6]  = W987;
        mp[7]  = e1;  mp[8]  = e3;  mp[9]  = e4;
        mp[10] = e43; mp[11] = e6;  mp[12] = e7;
        mp[13] = e76; mp[14] = e8;  mp[15] = e87;
        mp[16] = e876;
    }
    __syncthreads();

    // ---- Compose 8 sub-maps per chain, write g_W[chain][c][17] ----
    if (tid < 64) {
        const int u = tid;
        SigMap R = sig_load_f(sMaps + (size_t)u * 17);
#pragma unroll
        for (int q = 1; q < 8; q++)
            R = sig_compose(R, sig_load_f(sMaps + (size_t)(q * 64 + u) * 17));

        const int chain = b * 64 + u;
        float* wp = g_W + ((size_t)chain * NCH + c) * 17;
        wp[0]  = R.Y0;  wp[1]  = R.S2;  wp[2]  = R.S5;  wp[3]  = R.S9;
        wp[4]  = R.W54; wp[5]  = R.W98; wp[6]  = R.W987;
        wp[7]  = R.E1;  wp[8]  = R.E3;  wp[9]  = R.E4;  wp[10] = R.E43;
        wp[11] = R.E6;  wp[12] = R.E7;  wp[13] = R.E76;
        wp[14] = R.E8;  wp[15] = R.E87; wp[16] = R.E876;
    }
}

// ---------------- Combine: warp-tree composition over 32 chunks ----------------
__device__ __forceinline__ SigMap sig_shfl_down(const SigMap& m, int o) {
    SigMap r;
    r.Y0  = __shfl_down_sync(0xffffffffu, m.Y0,  o);
    r.S2  = __shfl_down_sync(0xffffffffu, m.S2,  o);
    r.S5  = __shfl_down_sync(0xffffffffu, m.S5,  o);
    r.S9  = __shfl_down_sync(0xffffffffu, m.S9,  o);
    r.W54 = __shfl_down_sync(0xffffffffu, m.W54, o);
    r.W98 = __shfl_down_sync(0xffffffffu, m.W98, o);
    r.W987= __shfl_down_sync(0xffffffffu, m.W987,o);
    r.E1  = __shfl_down_sync(0xffffffffu, m.E1,  o);
    r.E3  = __shfl_down_sync(0xffffffffu, m.E3,  o);
    r.E4  = __shfl_down_sync(0xffffffffu, m.E4,  o);
    r.E43 = __shfl_down_sync(0xffffffffu, m.E43, o);
    r.E6  = __shfl_down_sync(0xffffffffu, m.E6,  o);
    r.E7  = __shfl_down_sync(0xffffffffu, m.E7,  o);
    r.E76 = __shfl_down_sync(0xffffffffu, m.E76, o);
    r.E8  = __shfl_down_sync(0xffffffffu, m.E8,  o);
    r.E87 = __shfl_down_sync(0xffffffffu, m.E87, o);
    r.E876= __shfl_down_sync(0xffffffffu, m.E876,o);
    return r;
}

extern "C" __global__ void __launch_bounds__(256)
lrsig_combine(float* __restrict__ out)
{
    const int chain = blockIdx.x * 8 + (threadIdx.x >> 5);
    const int lane  = threadIdx.x & 31;

    const float* wp = g_W + ((size_t)chain * NCH + lane) * 17;
    SigMap M = sig_load_f(wp);   // chunk = lane (NCH = 32)

#pragma unroll
    for (int o = 1; o < 32; o <<= 1)
        M = sig_compose(M, sig_shfl_down(M, o));   // lane 0 exact after tree

    if (lane == 0) out[chain] = M.Y0;   // initial state zero -> Y = Y0
}

// ---------------- Launch ----------------
extern "C" void kernel_launch(void* const* d_in, const int* in_sizes, int n_in,
                              void* d_out, int out_size)
{
    const float* x    = (const float*)d_in[0];  // (32, 2048, 63) f32
    const float* kern = (const float*)d_in[1];  // (64, 10, 64)  f32

    cudaFuncSetAttribute(lrsig_fused, cudaFuncAttributeMaxDynamicSharedMemorySize,
                         SMEM_TOTAL);

    lrsig_prep<<<(FDIM * LUDIM + 255) / 256, 256>>>(kern);
    lrsig_fused<<<dim3(NCH, BB), 512, SMEM_TOTAL>>>(x, kern);
    lrsig_combine<<<NCHAIN / 8, 256>>>((float*)d_out);
}

// round 13
// speedup vs baseline: 1.4809x; 1.1139x over previous
#include <cuda_runtime.h>
#include <cuda_bf16.h>
#include <cstdint>
#include <cstddef>

// Problem constants
#define BB     32
#define TT     2048
#define FIN    63
#define FDIM   64
#define LUDIM  640
#define NCH    32      // chunks of 64 timesteps
#define TCH    64
#define NCHAIN 2048

// smem layout — total 113,664 B -> 2 CTAs/SM
#define XSTR   72      // dX row stride (bf16 elems)
#define KSTR   72      // K stage stride (bf16 elems): 64 cols + 8 pad
#define PSTR   260     // sP row stride (floats): 256 cols max per pass + 4 pad
#define OFF_XH 0
#define OFF_XL 9216            // 64*72*2
#define OFF_KH 18432           // 64*72*2 per buffer
#define OFF_KL 27648
#define OFF_MAPS 36864         // 4 subchunks * 64 u * 10 coeffs * 4B = 10240
#define OFF_SP 47104
#define SMEM_TOTAL (OFF_SP + TCH * PSTR * 4)   // 47104 + 66560 = 113664

// Precomputed bf16 hi/lo split of kernel, [f][lu]
__device__ __nv_bfloat16 g_KH[FDIM * LUDIM];
__device__ __nv_bfloat16 g_KL[FDIM * LUDIM];
// g_W layout: [chain][c][17]
__device__ float g_W[(size_t)NCHAIN * NCH * 17];

// ---------------- PTX helpers ----------------
__device__ __forceinline__ uint32_t smem_u32(const void* p) {
    uint32_t a;
    asm("{ .reg .u64 t; cvta.to.shared.u64 t, %1; cvt.u32.u64 %0, t; }" : "=r"(a) : "l"(p));
    return a;
}
__device__ __forceinline__ void ldsm_x4(uint32_t& r0, uint32_t& r1, uint32_t& r2, uint32_t& r3,
                                        uint32_t addr) {
    asm volatile("ldmatrix.sync.aligned.m8n8.x4.shared.b16 {%0,%1,%2,%3}, [%4];"
                 : "=r"(r0), "=r"(r1), "=r"(r2), "=r"(r3) : "r"(addr));
}
__device__ __forceinline__ void ldsm_x4t(uint32_t& r0, uint32_t& r1, uint32_t& r2, uint32_t& r3,
                                         uint32_t addr) {
    asm volatile("ldmatrix.sync.aligned.m8n8.x4.trans.shared.b16 {%0,%1,%2,%3}, [%4];"
                 : "=r"(r0), "=r"(r1), "=r"(r2), "=r"(r3) : "r"(addr));
}
__device__ __forceinline__ void mma_bf16(float* c, const uint32_t* a, uint32_t b0, uint32_t b1) {
    asm volatile(
        "mma.sync.aligned.m16n8k16.row.col.f32.bf16.bf16.f32 "
        "{%0,%1,%2,%3}, {%4,%5,%6,%7}, {%8,%9}, {%0,%1,%2,%3};"
        : "+f"(c[0]), "+f"(c[1]), "+f"(c[2]), "+f"(c[3])
        : "r"(a[0]), "r"(a[1]), "r"(a[2]), "r"(a[3]), "r"(b0), "r"(b1));
}

// ---------------- Chen map (combine kernel) ----------------
struct SigMap {
    float Y0,S2,S5,S9,W54,W98,W987,E1,E3,E4,E43,E6,E7,E76,E8,E87,E876;
};

__device__ __forceinline__ SigMap sig_compose(const SigMap& A, const SigMap& B) {
    SigMap C;
    C.E1   = A.E1 + B.E1;
    C.E3   = A.E3 + B.E3;
    C.E6   = A.E6 + B.E6;
    C.E4   = A.E4 + B.E4;
    C.E43  = A.E43 + A.E3 * B.E4 + B.E43;
    C.E7   = A.E7 + B.E7;
    C.E76  = A.E76 + A.E6 * B.E7 + B.E76;
    C.E8   = A.E8 + B.E8;
    C.E87  = A.E87 + A.E7 * B.E8 + B.E87;
    C.E876 = A.E876 + A.E76 * B.E8 + A.E6 * B.E87 + B.E876;
    C.S2   = A.S2 + B.S2;
    C.S5   = A.S5 + B.S5;
    C.S9   = A.S9 + B.S9;
    C.W54  = A.W54 + A.E4 * B.S5 + B.W54;
    C.W98  = A.W98 + A.E8 * B.S9 + B.W98;
    C.W987 = A.W987 + A.E87 * B.S9 + A.E7 * B.W98 + B.W987;
    C.Y0   = A.Y0 + B.Y0 + A.E1 * B.S2 + A.E43 * B.S5 + A.E3 * B.W54
           + A.E876 * B.S9 + A.E76 * B.W98 + A.E6 * B.W987;
    return C;
}

__device__ __forceinline__ SigMap sig_load_f(const float* mp) {
    SigMap m;
    m.Y0  = mp[0];  m.S2  = mp[1];  m.S5  = mp[2];  m.S9  = mp[3];
    m.W54 = mp[4];  m.W98 = mp[5];  m.W987= mp[6];
    m.E1  = mp[7];  m.E3  = mp[8];  m.E4  = mp[9];  m.E43 = mp[10];
    m.E6  = mp[11]; m.E7  = mp[12]; m.E76 = mp[13];
    m.E8  = mp[14]; m.E87 = mp[15]; m.E876= mp[16];
    return m;
}

// ---------------- Prep: K -> bf16 hi/lo in gmem ----------------
extern "C" __global__ void __launch_bounds__(256)
lrsig_prep(const float* __restrict__ kern)
{
    int i = blockIdx.x * 256 + threadIdx.x;
    if (i < FDIM * LUDIM) {
        float v = kern[i];
        __nv_bfloat16 hi = __float2bfloat16(v);
        g_KH[i] = hi;
        g_KL[i] = __float2bfloat16(v - __bfloat162float(hi));
    }
}

// ---------------- Fused kernel: m = dX @ K + 3-pass chunk scan ----------------
// Grid (NCH, BB) = (32, 32), 256 threads, 2 CTAs/SM (113.7 KB smem).
// 8 warps: wt = w&3 (16-row t quarter), wn = w>>2 (32-col half of 64-col stage).
// 10 stages of 64 lu cols (one level each); sP holds one PASS (<=256 cols):
//   pass A = levels 0-2 (stages 0-2), pass B = levels 3-5, pass C = levels 6-9.
// Each pass ends with its group's scan; sP is reused. Y0 accumulates in regs.
extern "C" __global__ void __launch_bounds__(256, 2)
lrsig_fused(const float* __restrict__ x, const float* __restrict__ kern)
{
    extern __shared__ char smem[];
    float* sP    = reinterpret_cast<float*>(smem + OFF_SP);
    float* sMaps = reinterpret_cast<float*>(smem + OFF_MAPS);
    const uint32_t sb = smem_u32(smem);

    const int tid  = threadIdx.x;
    const int lane = tid & 31;
    const int w    = tid >> 5;
    const int wt   = w & 3;
    const int wn   = w >> 2;
    const int c    = blockIdx.x;
    const int b    = blockIdx.y;
    const int t0   = c * TCH;

    // K prefetch: per stage buffer = 64 rows x 8 uint4 (data) = 512 uint4,
    // exactly 2 per thread. Dest rows are 9 uint4 (KSTR=72, pad never read).
    const uint4* srcH = reinterpret_cast<const uint4*>(g_KH);  // 80 uint4/row
    const uint4* srcL = reinterpret_cast<const uint4*>(g_KL);
    uint4* dstH = reinterpret_cast<uint4*>(smem + OFF_KH);
    uint4* dstL = reinterpret_cast<uint4*>(smem + OFF_KL);
    const int f0 = tid >> 3, v0 = tid & 7;
    const int f1 = f0 + 32;

    // Prefetch stage 0 (overlaps dX fill)
    uint4 rH0 = srcH[f0 * 80 + v0], rH1 = srcH[f1 * 80 + v0];
    uint4 rL0 = srcL[f0 * 80 + v0], rL1 = srcL[f1 * 80 + v0];

    // ---- dX tile (hi/lo bf16 split), [t][f], stride 72; exact fp32 diff ----
    for (int e = tid; e < TCH * FDIM; e += 256) {
        int tl = e >> 6, f = e & 63;
        int t = t0 + tl;
        float v;
        if (t == 0)      v = 0.0f;                                   // m[0] = 0
        else if (f < FIN) {
            const float* xr = x + ((size_t)b * TT + t) * FIN + f;
            v = xr[0] - xr[-FIN];
        } else            v = 2.0f / 2047.0f;                        // d(time)
        __nv_bfloat16 hi = __float2bfloat16(v);
        __nv_bfloat16 lo = __float2bfloat16(v - __bfloat162float(hi));
        int off = (tl * XSTR + f) * 2;
        *reinterpret_cast<__nv_bfloat16*>(smem + OFF_XH + off) = hi;
        *reinterpret_cast<__nv_bfloat16*>(smem + OFF_XL + off) = lo;
    }
    __syncthreads();

    // ---- Preload A fragments once (32 regs; reused across all 10 stages) ----
    const uint32_t a_off = (uint32_t)((lane & 15) * XSTR + ((lane >> 4) << 3)) * 2;
    uint32_t Ah[4][4], Al[4][4];
#pragma unroll
    for (int ks = 0; ks < 4; ks++) {
        uint32_t ra = (uint32_t)(wt * 16 * XSTR + ks * 16) * 2 + a_off;
        ldsm_x4(Ah[ks][0], Ah[ks][1], Ah[ks][2], Ah[ks][3], sb + OFF_XH + ra);
        ldsm_x4(Al[ks][0], Al[ks][1], Al[ks][2], Al[ks][3], sb + OFF_XL + ra);
    }

    const uint32_t b_off = (uint32_t)((((lane >> 3) & 1) * 8 + (lane & 7)) * KSTR
                                      + ((lane >> 4) << 3)) * 2;

    float Y0acc = 0.0f;   // accumulates y0+W21, +W543, +W9876 (tid<64 meaningful)

    // ---- Stage loop: 10 stages of 64 cols; passes end at j = 2, 5, 9 ----
    for (int j = 0; j < 10; j++) {
        if (j > 0) __syncthreads();   // prior ldsm/scan reads done before overwrite
        // Commit prefetched K stage to smem
        dstH[f0 * 9 + v0] = rH0;  dstH[f1 * 9 + v0] = rH1;
        dstL[f0 * 9 + v0] = rL0;  dstL[f1 * 9 + v0] = rL1;
        __syncthreads();
        if (j < 9) {
            rH0 = srcH[f0 * 80 + (j + 1) * 8 + v0];
            rH1 = srcH[f1 * 80 + (j + 1) * 8 + v0];
            rL0 = srcL[f0 * 80 + (j + 1) * 8 + v0];
            rL1 = srcL[f1 * 80 + (j + 1) * 8 + v0];
        }

        float C[4][4];
#pragma unroll
        for (int nt = 0; nt < 4; nt++)
#pragma unroll
            for (int i = 0; i < 4; i++) C[nt][i] = 0.0f;

#pragma unroll
        for (int ks = 0; ks < 4; ks++)
#pragma unroll
            for (int q = 0; q < 2; q++) {
                uint32_t rb = (uint32_t)(ks * 16 * KSTR + (wn * 32 + q * 16)) * 2 + b_off;
                uint32_t Bh[4], Bl[4];
                ldsm_x4t(Bh[0], Bh[1], Bh[2], Bh[3], sb + OFF_KH + rb);
                ldsm_x4t(Bl[0], Bl[1], Bl[2], Bl[3], sb + OFF_KL + rb);
#pragma unroll
                for (int p = 0; p < 2; p++) {
                    float* cc = C[q * 2 + p];
                    mma_bf16(cc, Ah[ks], Bh[p * 2], Bh[p * 2 + 1]);
                    mma_bf16(cc, Al[ks], Bh[p * 2], Bh[p * 2 + 1]);
                    mma_bf16(cc, Ah[ks], Bl[p * 2], Bl[p * 2 + 1]);
                }
            }

        // Epilogue into sP at pass-local columns
        {
            const int ps = (j < 3) ? 0 : ((j < 6) ? 3 : 6);
            const int cb = (j - ps) * 64;
            int r = wt * 16 + (lane >> 2);
#pragma unroll
            for (int nt = 0; nt < 4; nt++) {
                int col = cb + wn * 32 + nt * 8 + (lane & 3) * 2;
                float* q0 = sP + (size_t)r * PSTR + col;
                float* q1 = sP + (size_t)(r + 8) * PSTR + col;
                *reinterpret_cast<float2*>(q0) = make_float2(C[nt][0], C[nt][1]);
                *reinterpret_cast<float2*>(q1) = make_float2(C[nt][2], C[nt][3]);
            }
        }

        // ---- Pass-end scans ----
        if (j == 2 || j == 5 || j == 9) {
            __syncthreads();     // sP complete for this pass
            const int u  = tid & 63;
            const int qc = tid >> 6;        // 0..3, 16 rows each
            const int r0 = qc * 16;
            float* mp = sMaps + (size_t)(qc * 64 + u) * 10;

            if (j == 2) {
                // levels 0,1,2 at cols 0,64,128
                float y0 = 0.f, e1 = 0.f, S2 = 0.f, W21 = 0.f;
#pragma unroll 4
                for (int i = 0; i < 16; i++) {
                    const float* p = sP + (size_t)(r0 + i) * PSTR + u;
                    float m0 = p[0], m1 = p[64], m2 = p[128];
                    y0 += m0;
                    W21 = fmaf(m2, e1, W21);  S2 += m2;  e1 += m1;
                }
                mp[0] = y0; mp[1] = e1; mp[2] = S2; mp[3] = W21;
                __syncthreads();
                if (tid < 64) {
                    float Y = 0.f, E1 = 0.f, S2t = 0.f, W21t = 0.f;
#pragma unroll
                    for (int q = 0; q < 4; q++) {
                        const float* s = sMaps + (size_t)(q * 64 + tid) * 10;
                        W21t += E1 * s[2] + s[3];
                        E1   += s[1];  S2t += s[2];  Y += s[0];
                    }
                    Y0acc = Y + W21t;
                    float* wp = g_W + ((size_t)(b * 64 + tid) * NCH + c) * 17;
                    wp[7] = E1;  wp[1] = S2t;
                }
            } else if (j == 5) {
                // levels 3,4,5 at cols 0,64,128
                float e3=0.f,e4=0.f,e43=0.f,S5=0.f,W54=0.f,W543=0.f;
#pragma unroll 4
                for (int i = 0; i < 16; i++) {
                    const float* p = sP + (size_t)(r0 + i) * PSTR + u;
                    float m3 = p[0], m4 = p[64], m5 = p[128];
                    W54  = fmaf(m5, e4,  W54);
                    W543 = fmaf(m5, e43, W543);  S5 += m5;
                    e43  = fmaf(m4, e3,  e43);
                    e3 += m3;  e4 += m4;
                }
                mp[0]=e3; mp[1]=e4; mp[2]=e43; mp[3]=S5; mp[4]=W54; mp[5]=W543;
                __syncthreads();
                if (tid < 64) {
                    float E3=0.f,E4=0.f,E43=0.f,S5t=0.f,W54t=0.f,W543t=0.f;
#pragma unroll
                    for (int q = 0; q < 4; q++) {
                        const float* s = sMaps + (size_t)(q * 64 + tid) * 10;
                        W543t += E43 * s[3] + E3 * s[4] + s[5];
                        W54t  += E4 * s[3] + s[4];
                        E43   += E3 * s[1] + s[2];
                        E3 += s[0];  E4 += s[1];  S5t += s[3];
                    }
                    Y0acc += W543t;
                    float* wp = g_W + ((size_t)(b * 64 + tid) * NCH + c) * 17;
                    wp[8]=E3; wp[9]=E4; wp[10]=E43; wp[2]=S5t; wp[4]=W54t;
                }
            } else {
                // levels 6,7,8,9 at cols 0,64,128,192
                float e6=0.f,e7=0.f,e8=0.f,e76=0.f,e87=0.f,e876=0.f;
                float S9=0.f,W98=0.f,W987=0.f,W9876=0.f;
#pragma unroll 4
                for (int i = 0; i < 16; i++) {
                    const float* p = sP + (size_t)(r0 + i) * PSTR + u;
                    float m6 = p[0], m7 = p[64], m8 = p[128], m9 = p[192];
                    W98   = fmaf(m9, e8,   W98);
                    W987  = fmaf(m9, e87,  W987);
                    W9876 = fmaf(m9, e876, W9876);  S9 += m9;
                    e876  = fmaf(m8, e76,  e876);
                    e87   = fmaf(m8, e7,   e87);
                    e76   = fmaf(m7, e6,   e76);
                    e6 += m6;  e7 += m7;  e8 += m8;
                }
                mp[0]=e6; mp[1]=e7; mp[2]=e8; mp[3]=e76; mp[4]=e87;
                mp[5]=e876; mp[6]=S9; mp[7]=W98; mp[8]=W987; mp[9]=W9876;
                __syncthreads();
                if (tid < 64) {
                    float E6=0.f,E7=0.f,E8=0.f,E76=0.f,E87=0.f,E876=0.f;
                    float S9t=0.f,W98t=0.f,W987t=0.f,W9876t=0.f;
#pragma unroll
                    for (int q = 0; q < 4; q++) {
                        const float* s = sMaps + (size_t)(q * 64 + tid) * 10;
                        W9876t += E876 * s[6] + E76 * s[7] + E6 * s[8] + s[9];
                        W987t  += E87 * s[6] + E7 * s[7] + s[8];
                        W98t   += E8 * s[6] + s[7];
                        E876   += E76 * s[2] + E6 * s[4] + s[5];
                        E87    += E7 * s[2] + s[4];
                        E76    += E6 * s[1] + s[3];
                        E6 += s[0];  E7 += s[1];  E8 += s[2];  S9t += s[6];
                    }
                    Y0acc += W9876t;
                    float* wp = g_W + ((size_t)(b * 64 + tid) * NCH + c) * 17;
                    wp[11]=E6; wp[12]=E7; wp[13]=E76; wp[14]=E8; wp[15]=E87;
                    wp[16]=E876; wp[3]=S9t; wp[5]=W98t; wp[6]=W987t;
                    wp[0]=Y0acc;
                }
            }
        }
    }
}

// ---------------- Combine: warp-tree composition over 32 chunks ----------------
__device__ __forceinline__ SigMap sig_shfl_down(const SigMap& m, int o) {
    SigMap r;
    r.Y0  = __shfl_down_sync(0xffffffffu, m.Y0,  o);
    r.S2  = __shfl_down_sync(0xffffffffu, m.S2,  o);
    r.S5  = __shfl_down_sync(0xffffffffu, m.S5,  o);
    r.S9  = __shfl_down_sync(0xffffffffu, m.S9,  o);
    r.W54 = __shfl_down_sync(0xffffffffu, m.W54, o);
    r.W98 = __shfl_down_sync(0xffffffffu, m.W98, o);
    r.W987= __shfl_down_sync(0xffffffffu, m.W987,o);
    r.E1  = __shfl_down_sync(0xffffffffu, m.E1,  o);
    r.E3  = __shfl_down_sync(0xffffffffu, m.E3,  o);
    r.E4  = __shfl_down_sync(0xffffffffu, m.E4,  o);
    r.E43 = __shfl_down_sync(0xffffffffu, m.E43, o);
    r.E6  = __shfl_down_sync(0xffffffffu, m.E6,  o);
    r.E7  = __shfl_down_sync(0xffffffffu, m.E7,  o);
    r.E76 = __shfl_down_sync(0xffffffffu, m.E76, o);
    r.E8  = __shfl_down_sync(0xffffffffu, m.E8,  o);
    r.E87 = __shfl_down_sync(0xffffffffu, m.E87, o);
    r.E876= __shfl_down_sync(0xffffffffu, m.E876,o);
    return r;
}

extern "C" __global__ void __launch_bounds__(256)
lrsig_combine(float* __restrict__ out)
{
    const int chain = blockIdx.x * 8 + (threadIdx.x >> 5);
    const int lane  = threadIdx.x & 31;

    const float* wp = g_W + ((size_t)chain * NCH + lane) * 17;
    SigMap M = sig_load_f(wp);   // chunk = lane (NCH = 32)

#pragma unroll
    for (int o = 1; o < 32; o <<= 1)
        M = sig_compose(M, sig_shfl_down(M, o));   // lane 0 exact after tree

    if (lane == 0) out[chain] = M.Y0;   // initial state zero -> Y = Y0
}

// ---------------- Launch ----------------
extern "C" void kernel_launch(void* const* d_in, const int* in_sizes, int n_in,
                              void* d_out, int out_size)
{
    const float* x    = (const float*)d_in[0];  // (32, 2048, 63) f32
    const float* kern = (const float*)d_in[1];  // (64, 10, 64)  f32

    cudaFuncSetAttribute(lrsig_fused, cudaFuncAttributeMaxDynamicSharedMemorySize,
                         SMEM_TOTAL);

    lrsig_prep<<<(FDIM * LUDIM + 255) / 256, 256>>>(kern);
    lrsig_fused<<<dim3(NCH, BB), 256, SMEM_TOTAL>>>(x, kern);
    lrsig_combine<<<NCHAIN / 8, 256>>>((float*)d_out);
}